// round 13
// baseline (speedup 1.0000x reference)
#include <cuda_runtime.h>
#include <math.h>

#define NB 8
#define NT 8192
#define ND 2048
#define NROWS (NB * NT)
#define KSEL 2048          // NT * 0.25
#define GRID 592           // 4 CTAs/SM x 148 SMs (all co-resident wave 1)
#define NWARPS (GRID * 8)
#define CHUNK 2            // rows per work-steal grab
#define STASH 24           // per-warp stash capacity (avg rows/warp = 13.8)
#define GATE_CTAS 256
#define CAND_MAX 256

// Device-global scratch (no allocations). Ticket + barrier counts self-reset;
// generations monotonic -> graph-replay safe.
__device__ double   d_ea[NROWS];
__device__ double   d_eb0[NROWS];
__device__ double   d_part[GRID];
__device__ unsigned d_ticket;
__device__ unsigned d_cnt[2];
__device__ unsigned d_gen[2];

// Fast fp64 exp: Cody-Waite + 13-term poly, ~1e-15 rel err (R6/R7-validated:
// final fp32 g bits identical to libm; ordering gaps near k-th are ~1e-5).
__device__ __forceinline__ double fast_exp(double x)
{
    x = fmin(fmax(x, -700.0), 700.0);
    double k = rint(x * 1.4426950408889634074);
    double r = fma(-k, 6.93147180369123816490e-01, x);
    r = fma(-k, 1.90821492927058770002e-10, r);
    double p = 2.08767569878681e-09;
    p = fma(p, r, 2.50521083854417e-08);
    p = fma(p, r, 2.75573192239859e-07);
    p = fma(p, r, 2.75573192239859e-06);
    p = fma(p, r, 2.48015873015873e-05);
    p = fma(p, r, 1.98412698412698e-04);
    p = fma(p, r, 1.38888888888889e-03);
    p = fma(p, r, 8.33333333333333e-03);
    p = fma(p, r, 4.16666666666667e-02);
    p = fma(p, r, 1.66666666666667e-01);
    p = fma(p, r, 0.5);
    p = fma(p, r, 1.0);
    p = fma(p, r, 1.0);
    return p * __longlong_as_double((unsigned long long)((long long)k + 1023) << 52);
}

// ---------------------------------------------------------------------------
// Single persistent kernel, work-stealing phase A.
//  A) warps grab 2-row chunks from a global ticket (fast SMs take more work
//     -> removes the 1.10-1.17x between-SM spread a static partition exposes
//     at the grid barrier); per-row (dst,dch) stashed per-warp, fp64 exps
//     computed lane-parallel after the loop (hidden under memory stalls).
//  bar0 (592 arrivals; CTAs <256 wait) -> partial-reduce -> ma -> K.
//  B) gate: g = (1+ea+eb)/(1+ea+eb+ea*eb), Newton-recip division.
//  bar1 (256 arrivals; CTAs <8 wait) -> per-batch exact top-k (keys from L2).
// Deadlock-safety: spinners <=256/<=8; other CTAs arrive-and-exit; live for
// any occupancy >= 2 CTAs/SM (have 4).
// ---------------------------------------------------------------------------
__global__ void __launch_bounds__(256, 4) mega_kernel(
    const float4* __restrict__ a, const float4* __restrict__ p,
    const float* __restrict__ oce, const float* __restrict__ mcu,
    const float* __restrict__ bce, const float* __restrict__ bcu,
    float* __restrict__ out)
{
    __shared__ int      s_hist[8 * 256];   // 8 KB (select phase)
    __shared__ float    s_sdst[8][STASH];
    __shared__ float    s_sdch[8][STASH];
    __shared__ int      s_srow[8][STASH];
    __shared__ double   s_dsum[8];
    __shared__ double   s_red[8];
    __shared__ double   s_ma;
    __shared__ int      s_warp_tot[8];
    __shared__ unsigned s_pref, s_thresh;
    __shared__ int      s_remk, s_ce, s_c2, s_cnt, s_need, s_ceq;
    __shared__ unsigned s_cand[CAND_MAX];

    const int tid  = threadIdx.x;
    const int warp = tid >> 5;
    const int lane = tid & 31;
    const int cta  = blockIdx.x;

    // scalar params (fp32, uniform, cheap) — needed by the exp tail
    const float xce = bce[0], xcu = bcu[0];
    const float bce_p = fmaxf(xce, 0.0f) + log1pf(expf(-fabsf(xce)));
    const float bcu_p = fmaxf(xcu, 0.0f) + log1pf(expf(-fabsf(xcu)));
    const float logoce = logf(oce[0] + 1e-10f);

    // ---------------- Phase A: work-stealing row reductions ----------------
    double dsum = 0.0;
    int myc = 0;   // warp-uniform processed-row count
    for (;;) {
        unsigned c;
        if (lane == 0) c = atomicAdd(&d_ticket, 1u);
        c = __shfl_sync(0xFFFFFFFFu, c, 0);
        const int r0 = (int)c * CHUNK;
        if (r0 >= NROWS) break;
#pragma unroll
        for (int rr = r0; rr < r0 + CHUNK; ++rr) {
            const size_t base = (size_t)rr * (ND / 4);
            float s_st = 0.0f, s_ch = 0.0f;
#pragma unroll
            for (int j = 0; j < 16; ++j) {
                float4 av = __ldg(&a[base + lane + 32 * j]);
                float4 pv = __ldg(&p[base + lane + 32 * j]);
                s_st += av.x * av.x + av.y * av.y + av.z * av.z + av.w * av.w;
                float dx = av.x - pv.x, dy = av.y - pv.y;
                float dz = av.z - pv.z, dw = av.w - pv.w;
                s_ch += dx * dx + dy * dy + dz * dz + dw * dw;
            }
#pragma unroll
            for (int off = 16; off > 0; off >>= 1) {
                s_st += __shfl_down_sync(0xFFFFFFFFu, s_st, off);
                s_ch += __shfl_down_sync(0xFFFFFFFFu, s_ch, off);
            }
            if (lane == 0) {
                const float invd = 1.0f / (float)ND;
                const float dst = s_st * invd;
                const float dch = s_ch * invd;
                dsum += (double)dst;
                if (myc < STASH) {
                    s_sdst[warp][myc] = dst;
                    s_sdch[warp][myc] = dch;
                    s_srow[warp][myc] = rr;
                } else {
                    // pathological overflow: inline exps (correct, rare)
                    const double CE = (double)dst - ((double)dch - (double)logoce);
                    d_ea[rr]  = fast_exp(-(double)bce_p * CE);
                    d_eb0[rr] = fast_exp(-(double)bcu_p * (double)dst);
                }
            }
            ++myc;   // all lanes -> stays warp-uniform
        }
    }

    // lane-parallel batched exp tail over this warp's stash (same warp wrote
    // it; smem visibility within warp via __syncwarp)
    __syncwarp();
    {
        const int cnt = myc < STASH ? myc : STASH;
        for (int e = lane; e < cnt; e += 32) {
            const float dst = s_sdst[warp][e];
            const float dch = s_sdch[warp][e];
            const int   rr  = s_srow[warp][e];
            const double CE = (double)dst - ((double)dch - (double)logoce);
            d_ea[rr]  = fast_exp(-(double)bce_p * CE);
            d_eb0[rr] = fast_exp(-(double)bcu_p * (double)dst);
        }
    }
    if (lane == 0) s_dsum[warp] = dsum;
    __syncthreads();
    if (tid == 0) {
        double ps = 0.0;
#pragma unroll
        for (int i = 0; i < 8; ++i) ps += s_dsum[i];
        d_part[cta] = ps;
    }

    // ---------------- barrier 0 (592 arrivals; gate CTAs wait) --------------
    __syncthreads();
    if (tid == 0) {
        __threadfence();                       // release d_ea/d_eb0/d_part
        const unsigned g0 = *(volatile unsigned*)&d_gen[0];
        const unsigned c  = atomicAdd(&d_cnt[0], 1u);
        if (c == GRID - 1) {
            d_cnt[0] = 0;
            __threadfence();
            atomicAdd(&d_gen[0], 1u);
        } else if (cta < GATE_CTAS) {
            while (*(volatile unsigned*)&d_gen[0] == g0) __nanosleep(128);
        }
        __threadfence();                       // acquire
    }
    __syncthreads();
    if (cta >= GATE_CTAS) return;              // arrived; slot freed
    if (cta == 0 && tid == 0) d_ticket = 0;    // reset for next replay

    // ---------------- mean -> K (fixed index order, deterministic) ---------
    {
        double v = 0.0;
        for (int i = tid; i < GRID; i += 256) v += __ldcg(&d_part[i]);
#pragma unroll
        for (int off = 16; off > 0; off >>= 1)
            v += __shfl_down_sync(0xFFFFFFFFu, v, off);
        if (lane == 0) s_red[warp] = v;
        __syncthreads();
        if (tid == 0) {
            double tot = 0.0;
#pragma unroll
            for (int i = 0; i < 8; ++i) tot += s_red[i];
            s_ma = tot / (double)NROWS;
        }
        __syncthreads();
    }
    const double K = fast_exp((double)bcu_p * (double)mcu[0] * s_ma);

    // ---------------- Phase B: gate (64K elems over 256 CTAs) ---------------
    {
        const int idx = cta * 256 + tid;
        const double ea   = __ldcg(&d_ea[idx]);
        const double eb   = __ldcg(&d_eb0[idx]) * K;
        const double num  = 1.0 + ea + eb;
        const double den  = num + ea * eb;
        double rcp = (double)__frcp_rn((float)den);
        rcp = fma(fma(-den, rcp, 1.0), rcp, rcp);   // Newton 1
        rcp = fma(fma(-den, rcp, 1.0), rcp, rcp);   // Newton 2 -> ~0.5 ulp
        out[idx] = (float)(num * rcp);
    }

    // ---------------- barrier 1 (256 arrivals; CTAs <8 wait) ----------------
    __syncthreads();
    if (tid == 0) {
        __threadfence();                       // release g writes
        const unsigned g0 = *(volatile unsigned*)&d_gen[1];
        const unsigned c  = atomicAdd(&d_cnt[1], 1u);
        if (c == GATE_CTAS - 1) {
            d_cnt[1] = 0;
            __threadfence();
            atomicAdd(&d_gen[1], 1u);
        } else if (cta < NB) {
            while (*(volatile unsigned*)&d_gen[1] == g0) __nanosleep(128);
        }
        __threadfence();                       // acquire
    }
    __syncthreads();
    if (cta >= NB) return;

    // ---------------- Phase C: per-batch exact top-k (CTA b = batch b) ------
    // Keys re-read from L2 each pass (32 KB/CTA/pass; warm, trivial).
    const int b = cta;
    const float* gb = out + b * NT;
#pragma unroll
    for (int i = 0; i < 8; ++i) s_hist[tid + i * 256] = 0;
    if (tid == 0) { s_pref = 0u; s_remk = KSEL; s_ce = 0; s_c2 = 0; s_cnt = 0; }
    __syncthreads();

    // two radix passes over the top two bytes
    for (int shift = 24; shift >= 16; shift -= 8) {
        const unsigned pref = s_pref;
        const int remk = s_remk;
        const unsigned msk = (shift == 24) ? 0u : 0xFF000000u;

        int* myhist = s_hist + warp * 256;
#pragma unroll
        for (int k = 0; k < 32; ++k) {
            const unsigned u = __float_as_uint(__ldcg(&gb[tid + k * 256]));
            const bool ok = ((u & msk) == pref);
            const int bin = (u >> shift) & 0xFF;
            const unsigned active = __ballot_sync(0xFFFFFFFFu, ok);
            if (ok) {
                const unsigned peers = __match_any_sync(active, bin);
                if (lane == (__ffs(peers) - 1))
                    myhist[bin] += __popc(peers);
            }
        }
        __syncthreads();

        int v = 0;
#pragma unroll
        for (int w = 0; w < 8; ++w) v += s_hist[w * 256 + (255 - tid)];
        int x = v;
#pragma unroll
        for (int off = 1; off < 32; off <<= 1) {
            const int y = __shfl_up_sync(0xFFFFFFFFu, x, off);
            if (lane >= off) x += y;
        }
        if (lane == 31) s_warp_tot[warp] = x;
        __syncthreads();
        {
            int offset = 0;
            for (int w = 0; w < warp; ++w) offset += s_warp_tot[w];
            const int cum  = x + offset;
            const int prev = cum - v;
            if (prev < remk && cum >= remk) {
                s_pref = pref | ((unsigned)(255 - tid) << shift);
                s_remk = remk - prev;
                if (shift == 16) s_c2 = v;
            }
        }
#pragma unroll
        for (int i = 0; i < 8; ++i) s_hist[tid + i * 256] = 0;
        __syncthreads();
    }

    const int c2 = s_c2;
    const int remk2 = s_remk;
    const unsigned pref2 = s_pref;

    if (c2 <= CAND_MAX) {
#pragma unroll
        for (int k = 0; k < 32; ++k) {
            const unsigned u = __float_as_uint(__ldcg(&gb[tid + k * 256]));
            if ((u & 0xFFFF0000u) == pref2) {
                const int pos = atomicAdd(&s_cnt, 1);
                if (pos < CAND_MAX) s_cand[pos] = u;
            }
        }
        __syncthreads();
        if (tid < c2) {
            const unsigned vi = s_cand[tid];
            int greater = 0, equal = 0;
            for (int j = 0; j < c2; ++j) {
                const unsigned vj = s_cand[j];
                greater += (vj > vi);
                equal   += (vj == vi);
            }
            if (greater < remk2 && remk2 <= greater + equal) {
                s_thresh = vi; s_need = remk2 - greater; s_ceq = equal;
            }
        }
        __syncthreads();
    } else {
        // exact fallback: remaining byte passes (hist already zeroed)
        for (int shift = 8; shift >= 0; shift -= 8) {
            const unsigned pref = s_pref;
            const int remk = s_remk;
            const unsigned msk = 0xFFFFFFFFu << (shift + 8);

            int* myhist = s_hist + warp * 256;
#pragma unroll
            for (int k = 0; k < 32; ++k) {
                const unsigned u = __float_as_uint(__ldcg(&gb[tid + k * 256]));
                const bool ok = ((u & msk) == pref);
                const int bin = (u >> shift) & 0xFF;
                const unsigned active = __ballot_sync(0xFFFFFFFFu, ok);
                if (ok) {
                    const unsigned peers = __match_any_sync(active, bin);
                    if (lane == (__ffs(peers) - 1))
                        myhist[bin] += __popc(peers);
                }
            }
            __syncthreads();

            int v = 0;
#pragma unroll
            for (int w = 0; w < 8; ++w) v += s_hist[w * 256 + (255 - tid)];
            int x = v;
#pragma unroll
            for (int off = 1; off < 32; off <<= 1) {
                const int y = __shfl_up_sync(0xFFFFFFFFu, x, off);
                if (lane >= off) x += y;
            }
            if (lane == 31) s_warp_tot[warp] = x;
            __syncthreads();
            {
                int offset = 0;
                for (int w = 0; w < warp; ++w) offset += s_warp_tot[w];
                const int cum  = x + offset;
                const int prev = cum - v;
                if (prev < remk && cum >= remk) {
                    s_pref = pref | ((unsigned)(255 - tid) << shift);
                    s_remk = remk - prev;
                    if (shift == 0) s_ce = v;
                }
            }
            if (shift > 0) {
#pragma unroll
                for (int i = 0; i < 8; ++i) s_hist[tid + i * 256] = 0;
            }
            __syncthreads();
        }
        if (tid == 0) { s_thresh = s_pref; s_need = s_remk; s_ceq = s_ce; }
        __syncthreads();
    }

    const unsigned thresh = s_thresh;
    const int need_eq = s_need;
    const int c_eq = s_ceq;

    // write binary mask (second output half)
    float* mout = out + NROWS + b * NT;
#pragma unroll
    for (int k = 0; k < 32; ++k) {
        const int i = tid + k * 256;
        const unsigned u = __float_as_uint(__ldcg(&gb[i]));
        float mval;
        if (u > thresh)      mval = 1.0f;
        else if (u < thresh) mval = 0.0f;
        else if (c_eq == need_eq) mval = 1.0f;      // no over-tie (common)
        else {
            // rare exact fp32 tie: lower index wins (jax.lax.top_k)
            int rnk = 0;
            for (int j = 0; j < i; ++j)
                if (__float_as_uint(__ldcg(&gb[j])) == thresh) ++rnk;
            mval = (rnk < need_eq) ? 1.0f : 0.0f;
        }
        mout[i] = mval;
    }
}

// ---------------------------------------------------------------------------
extern "C" void kernel_launch(void* const* d_in, const int* in_sizes, int n_in,
                              void* d_out, int out_size)
{
    const float4* a = (const float4*)d_in[0];   // actual_residual   [8,8192,2048] f32
    const float4* p = (const float4*)d_in[1];   // predicted_residual[8,8192,2048] f32
    const float* oce = (const float*)d_in[2];
    const float* mcu = (const float*)d_in[3];
    const float* bce = (const float*)d_in[4];
    const float* bcu = (const float*)d_in[5];
    float* out = (float*)d_out;                  // [2, 8, 8192]: g then binary mask

    mega_kernel<<<GRID, 256>>>(a, p, oce, mcu, bce, bcu, out);
}

// round 14
// speedup vs baseline: 1.2446x; 1.2446x over previous
#include <cuda_runtime.h>
#include <math.h>

#define NB 8
#define NT 8192
#define ND 2048
#define NROWS (NB * NT)
#define KSEL 2048      // NT * 0.25

// Scratch + counters (device globals; no allocations). Counters reset by
// their consumer before kernel exit -> graph-replay safe.
__device__ double d_ea[NROWS];        // exp(-bce_p * CE)   per row
__device__ double d_eb0[NROWS];       // exp(-bcu_p * D_st) per row
__device__ double d_part[NROWS / 8];  // per-CTA fp64 partial sums of D_st
__device__ double d_K;                // exp(bcu_p * m * ma)
__device__ int    d_ctr1;
__device__ int    d_ctr2[NB];

// Fast fp64 exp: Cody-Waite reduction + 13-term poly; ~1e-15 rel accuracy
// (R6/R7-validated: final fp32 g bits stable; ordering gaps are ~1e-5).
__device__ __forceinline__ double fast_exp(double x)
{
    x = fmin(fmax(x, -700.0), 700.0);
    double k = rint(x * 1.4426950408889634074);
    double r = fma(-k, 6.93147180369123816490e-01, x);
    r = fma(-k, 1.90821492927058770002e-10, r);
    double p = 2.08767569878681e-09;
    p = fma(p, r, 2.50521083854417e-08);
    p = fma(p, r, 2.75573192239859e-07);
    p = fma(p, r, 2.75573192239859e-06);
    p = fma(p, r, 2.48015873015873e-05);
    p = fma(p, r, 1.98412698412698e-04);
    p = fma(p, r, 1.38888888888889e-03);
    p = fma(p, r, 8.33333333333333e-03);
    p = fma(p, r, 4.16666666666667e-02);
    p = fma(p, r, 1.66666666666667e-01);
    p = fma(p, r, 0.5);
    p = fma(p, r, 1.0);
    p = fma(p, r, 1.0);
    return p * __longlong_as_double((unsigned long long)((long long)k + 1023) << 52);
}

// ---------------------------------------------------------------------------
// Kernel 1 (byte-identical compute to the 175.9us champion): warp-per-row
// squared-norm reductions at the LTS/HBM cap; per-row fp64 exps in a one-warp
// CTA tail (hidden under memory stalls); last-arriving CTA computes the
// global mean -> scalar K. NEW: every CTA signals griddepcontrol.launch_
// dependents at exit (last CTA after d_K write) so the PDL-launched kernel2
// can roll out overlapped with this kernel's tail/teardown.
// ---------------------------------------------------------------------------
__global__ void __launch_bounds__(256) row_reduce_kernel(
    const float4* __restrict__ a, const float4* __restrict__ p,
    const float* __restrict__ oce, const float* __restrict__ mcu,
    const float* __restrict__ bce, const float* __restrict__ bcu)
{
    const int warp = threadIdx.x >> 5;
    const int lane = threadIdx.x & 31;
    const int row  = blockIdx.x * 8 + warp;
    const size_t base = (size_t)row * (ND / 4);

    float s_st = 0.0f, s_ch = 0.0f;
#pragma unroll
    for (int j = 0; j < 16; ++j) {
        const size_t idx = base + lane + 32 * j;
        float4 av = __ldg(&a[idx]);
        float4 pv = __ldg(&p[idx]);
        s_st += av.x * av.x + av.y * av.y + av.z * av.z + av.w * av.w;
        float dx = av.x - pv.x, dy = av.y - pv.y;
        float dz = av.z - pv.z, dw = av.w - pv.w;
        s_ch += dx * dx + dy * dy + dz * dz + dw * dw;
    }

#pragma unroll
    for (int off = 16; off > 0; off >>= 1) {
        s_st += __shfl_down_sync(0xFFFFFFFFu, s_st, off);
        s_ch += __shfl_down_sync(0xFFFFFFFFu, s_ch, off);
    }

    __shared__ float sh_dst[8], sh_dch[8];
    if (lane == 0) {
        const float invd = 1.0f / (float)ND;
        sh_dst[warp] = s_st * invd;
        sh_dch[warp] = s_ch * invd;
    }
    __syncthreads();

    // CTA tail: 8 lanes compute the 2 fp64 exps per row + CTA partial sum.
    if (threadIdx.x < 8) {
        const float xce = bce[0], xcu = bcu[0];
        const float bce_p = fmaxf(xce, 0.0f) + log1pf(expf(-fabsf(xce)));
        const float bcu_p = fmaxf(xcu, 0.0f) + log1pf(expf(-fabsf(xcu)));
        const float logoce = logf(oce[0] + 1e-10f);

        const int r = blockIdx.x * 8 + threadIdx.x;
        const double dst = (double)sh_dst[threadIdx.x];
        const double dch = (double)sh_dch[threadIdx.x];
        const double CE = dst - (dch - (double)logoce);
        d_ea[r]  = fast_exp(-(double)bce_p * CE);
        d_eb0[r] = fast_exp(-(double)bcu_p * dst);

        if (threadIdx.x == 0) {
            double ps = 0.0;
#pragma unroll
            for (int i = 0; i < 8; ++i) ps += (double)sh_dst[i];
            d_part[blockIdx.x] = ps;
        }
    }

    // last-CTA: global mean of D_st -> scalar K
    __shared__ int s_last;
    __threadfence();
    __syncthreads();
    if (threadIdx.x == 0)
        s_last = (atomicAdd(&d_ctr1, 1) == (int)gridDim.x - 1);
    __syncthreads();
    if (!s_last) {
        // writes (d_ea/d_eb0/d_part) are program-ordered before this signal
        asm volatile("griddepcontrol.launch_dependents;" ::: "memory");
        return;
    }
    __threadfence();

    const int t = threadIdx.x;
    double a0 = 0.0, a1 = 0.0, a2 = 0.0, a3 = 0.0;
#pragma unroll
    for (int j = 0; j < 8; ++j) {
        a0 += __ldcg(&d_part[t + (4 * j + 0) * 256]);
        a1 += __ldcg(&d_part[t + (4 * j + 1) * 256]);
        a2 += __ldcg(&d_part[t + (4 * j + 2) * 256]);
        a3 += __ldcg(&d_part[t + (4 * j + 3) * 256]);
    }
    double s = (a0 + a1) + (a2 + a3);
#pragma unroll
    for (int off = 16; off > 0; off >>= 1)
        s += __shfl_down_sync(0xFFFFFFFFu, s, off);
    __shared__ double ws[8];
    if (lane == 0) ws[warp] = s;
    __syncthreads();
    if (t == 0) {
        double tot = 0.0;
#pragma unroll
        for (int i = 0; i < 8; ++i) tot += ws[i];
        const double ma = tot / (double)NROWS;
        const float xcu = bcu[0];
        const float bcu_p = fmaxf(xcu, 0.0f) + log1pf(expf(-fabsf(xcu)));
        d_K = fast_exp((double)bcu_p * (double)mcu[0] * ma);
        d_ctr1 = 0;   // reset for next graph replay
    }
    __syncthreads();   // d_K write ordered before the last CTA's signal
    asm volatile("griddepcontrol.launch_dependents;" ::: "memory");
}

// ---------------------------------------------------------------------------
// Kernel 2 (byte-identical compute to the 175.9us champion): gate (exp-free,
// Newton-recip division) fused with per-batch exact top-k in the last-
// arriving CTA of each batch. NEW: launched with programmatic stream
// serialization; preamble (index math, state init) runs pre-wait, then
// griddepcontrol.wait guarantees kernel1's writes are visible.
// ---------------------------------------------------------------------------
__global__ void __launch_bounds__(1024) gate_select_kernel(float* __restrict__ out)
{
    const int b    = blockIdx.x >> 4;
    const int seg  = blockIdx.x & 15;
    const int t    = threadIdx.x;
    const int warp = t >> 5;
    const int lane = t & 31;

    __shared__ int hist[32 * 256];   // warp-private rows, 32KB
    __shared__ int warp_tot[8];
    __shared__ unsigned s_pref;
    __shared__ int s_remk, s_ce, s_c2, s_cnt, s_need, s_ceq;
    __shared__ unsigned s_cand[256];
    __shared__ unsigned s_thresh;
    __shared__ int s_last;

    // PDL: block here until kernel1's writes (d_ea/d_eb0/d_K) are visible.
    asm volatile("griddepcontrol.wait;" ::: "memory");

    // ---- gate phase: 512 elements per CTA ----
    if (t < 512) {
        const double K = d_K;
        const int idx = b * NT + seg * 512 + t;
        const double ea   = d_ea[idx];
        const double eb   = d_eb0[idx] * K;
        const double prod = ea * eb;
        const double num  = 1.0 + ea + eb;
        const double den  = num + prod;
        double g;
        if (den < 1e30) {   // always true for this data (den ~ O(10))
            double r = (double)__frcp_rn((float)den);
            r = fma(fma(-den, r, 1.0), r, r);   // Newton 1: ~2^-46
            r = fma(fma(-den, r, 1.0), r, r);   // Newton 2: ~2^-53
            g = num * r;
        } else {
            g = num / den;  // defensive exact path
        }
        out[idx] = (float)g;
    }

    // ---- handshake: last CTA of this batch runs the select ----
    __threadfence();
    __syncthreads();
    if (t == 0)
        s_last = (atomicAdd(&d_ctr2[b], 1) == 15);
    __syncthreads();
    if (!s_last) return;
    __threadfence();
    if (t == 0) d_ctr2[b] = 0;   // reset for next graph replay

    // ---- select phase: exact top-k radix select on fp32 bit patterns ----
    const float* gb = out + b * NT;
    unsigned uv[8];                  // whole batch cached: 1024 thr x 8 keys
#pragma unroll
    for (int it = 0; it < 8; ++it)
        uv[it] = __float_as_uint(__ldcg(&gb[t + it * 1024]));

    if (t == 0) { s_pref = 0u; s_remk = KSEL; s_ce = 0; s_c2 = 0; s_cnt = 0; }
#pragma unroll
    for (int i = 0; i < 8; ++i) hist[t + i * 1024] = 0;
    __syncthreads();

    // -- radix passes on the top two bytes --
    for (int shift = 24; shift >= 16; shift -= 8) {
        const unsigned pref = s_pref;
        const int remk = s_remk;
        const unsigned msk = (shift == 24) ? 0u : 0xFF000000u;

        int* myhist = hist + warp * 256;
#pragma unroll
        for (int it = 0; it < 8; ++it) {
            const unsigned u = uv[it];
            const bool ok = ((u & msk) == pref);
            const int bin = (u >> shift) & 0xFF;
            const unsigned active = __ballot_sync(0xFFFFFFFFu, ok);
            if (ok) {
                const unsigned peers = __match_any_sync(active, bin);
                if (lane == (__ffs(peers) - 1))
                    myhist[bin] += __popc(peers);
            }
        }
        __syncthreads();

        int v = 0, x = 0;
        if (t < 256) {
            const int bin = 255 - t;
#pragma unroll
            for (int w = 0; w < 32; ++w) v += hist[w * 256 + bin];
            x = v;
#pragma unroll
            for (int off = 1; off < 32; off <<= 1) {
                const int y = __shfl_up_sync(0xFFFFFFFFu, x, off);
                if (lane >= off) x += y;
            }
            if (lane == 31) warp_tot[warp] = x;
        }
        __syncthreads();
        if (t < 256) {
            int offset = 0;
            for (int w = 0; w < warp; ++w) offset += warp_tot[w];
            const int cum  = x + offset;
            const int prev = cum - v;
            if (prev < remk && cum >= remk) {
                s_pref = pref | ((unsigned)(255 - t) << shift);
                s_remk = remk - prev;
                if (shift == 16) s_c2 = v;   // candidate count at 16-bit prefix
            }
        }
#pragma unroll
        for (int i = 0; i < 8; ++i) hist[t + i * 1024] = 0;  // for next pass
        __syncthreads();
    }

    const int c2        = s_c2;
    const int remk2     = s_remk;
    const unsigned pref2 = s_pref;

    if (c2 <= 256) {
        // -- gather the prefix-matching candidates, rank-count the threshold --
#pragma unroll
        for (int it = 0; it < 8; ++it) {
            const unsigned u = uv[it];
            if ((u & 0xFFFF0000u) == pref2) {
                const int pos = atomicAdd(&s_cnt, 1);
                if (pos < 256) s_cand[pos] = u;
            }
        }
        __syncthreads();
        if (t < c2) {
            const unsigned vi = s_cand[t];
            int greater = 0, equal = 0;
            for (int j = 0; j < c2; ++j) {
                const unsigned vj = s_cand[j];
                greater += (vj > vi);
                equal   += (vj == vi);
            }
            if (greater < remk2 && remk2 <= greater + equal) {
                s_thresh = vi;
                s_need   = remk2 - greater;
                s_ceq    = equal;
            }
        }
        __syncthreads();
    } else {
        // -- exact fallback: passes over bytes 1 and 0 (hist is zeroed) --
        for (int shift = 8; shift >= 0; shift -= 8) {
            const unsigned pref = s_pref;
            const int remk = s_remk;
            const unsigned msk = 0xFFFFFFFFu << (shift + 8);

            int* myhist = hist + warp * 256;
#pragma unroll
            for (int it = 0; it < 8; ++it) {
                const unsigned u = uv[it];
                const bool ok = ((u & msk) == pref);
                const int bin = (u >> shift) & 0xFF;
                const unsigned active = __ballot_sync(0xFFFFFFFFu, ok);
                if (ok) {
                    const unsigned peers = __match_any_sync(active, bin);
                    if (lane == (__ffs(peers) - 1))
                        myhist[bin] += __popc(peers);
                }
            }
            __syncthreads();

            int v = 0, x = 0;
            if (t < 256) {
                const int bin = 255 - t;
#pragma unroll
                for (int w = 0; w < 32; ++w) v += hist[w * 256 + bin];
                x = v;
#pragma unroll
                for (int off = 1; off < 32; off <<= 1) {
                    const int y = __shfl_up_sync(0xFFFFFFFFu, x, off);
                    if (lane >= off) x += y;
                }
                if (lane == 31) warp_tot[warp] = x;
            }
            __syncthreads();
            if (t < 256) {
                int offset = 0;
                for (int w = 0; w < warp; ++w) offset += warp_tot[w];
                const int cum  = x + offset;
                const int prev = cum - v;
                if (prev < remk && cum >= remk) {
                    s_pref = pref | ((unsigned)(255 - t) << shift);
                    s_remk = remk - prev;
                    if (shift == 0) s_ce = v;
                }
            }
            if (shift > 0) {
#pragma unroll
                for (int i = 0; i < 8; ++i) hist[t + i * 1024] = 0;
            }
            __syncthreads();
        }
        if (t == 0) { s_thresh = s_pref; s_need = s_remk; s_ceq = s_ce; }
        __syncthreads();
    }

    const unsigned thresh = s_thresh;
    const int need_eq = s_need;
    const int c_eq = s_ceq;

    // ---- write binary mask (second output half) ----
    float* mout = out + NROWS + b * NT;
#pragma unroll
    for (int it = 0; it < 8; ++it) {
        const int i = t + it * 1024;
        const unsigned u = uv[it];
        float mval;
        if (u > thresh)      mval = 1.0f;
        else if (u < thresh) mval = 0.0f;
        else if (c_eq == need_eq) mval = 1.0f;          // no over-tie (common)
        else {
            // rare exact fp32 tie at threshold: lower index wins (lax.top_k)
            int r = 0;
            for (int j = 0; j < i; ++j)
                if (__float_as_uint(__ldcg(&gb[j])) == thresh) ++r;
            mval = (r < need_eq) ? 1.0f : 0.0f;
        }
        mout[i] = mval;
    }
}

// ---------------------------------------------------------------------------
extern "C" void kernel_launch(void* const* d_in, const int* in_sizes, int n_in,
                              void* d_out, int out_size)
{
    const float4* a = (const float4*)d_in[0];   // actual_residual   [8,8192,2048] f32
    const float4* p = (const float4*)d_in[1];   // predicted_residual[8,8192,2048] f32
    const float* oce = (const float*)d_in[2];
    const float* mcu = (const float*)d_in[3];
    const float* bce = (const float*)d_in[4];
    const float* bcu = (const float*)d_in[5];
    float* out = (float*)d_out;                  // [2, 8, 8192]: g then binary mask

    row_reduce_kernel<<<NROWS / 8, 256>>>(a, p, oce, mcu, bce, bcu);

    // PDL launch: kernel2 rolls out overlapped with kernel1's tail/teardown;
    // griddepcontrol.wait inside provides the data dependency.
    cudaLaunchConfig_t cfg = {};
    cfg.gridDim  = dim3(NB * 16);
    cfg.blockDim = dim3(1024);
    cfg.dynamicSmemBytes = 0;
    cfg.stream = 0;
    cudaLaunchAttribute attr[1];
    attr[0].id = cudaLaunchAttributeProgrammaticStreamSerialization;
    attr[0].val.programmaticStreamSerializationAllowed = 1;
    cfg.attrs = attr;
    cfg.numAttrs = 1;
    cudaLaunchKernelEx(&cfg, gate_select_kernel, out);
}